// round 3
// baseline (speedup 1.0000x reference)
#include <cuda_runtime.h>

#define NB 32      // batch
#define NT 2048    // tokens
#define ND 1024    // d_token == n_heads*d_head
#define TS 16      // token splits for the reduction
#define TOK (NT/TS)
#define KS2 8      // GEMM K-splits (K-slice = 128 floats = 32 float4)
#define OT 64      // o-columns per GEMM block tile

// Scratch (allocation-free: __device__ globals)
__device__ float g_partial[TS * NB * ND];   // 8 MB reduce partials
__device__ float g_xc[KS2][NB * ND];        // GEMM1 K-split partials
__device__ float g_op[KS2][NB * ND];        // GEMM2 K-split partials

// ---------------------------------------------------------------------------
// packed fp32x2 helpers (sm_100+): d += a * b elementwise on packed pairs
// ---------------------------------------------------------------------------
__device__ __forceinline__ void ffma2(unsigned long long& d,
                                      unsigned long long a,
                                      unsigned long long b) {
    asm("fma.rn.f32x2 %0, %1, %2, %0;" : "+l"(d) : "l"(a), "l"(b));
}
__device__ __forceinline__ void lds_v2u64(unsigned long long& lo,
                                          unsigned long long& hi,
                                          unsigned addr) {
    asm volatile("ld.shared.v2.u64 {%0, %1}, [%2];"
                 : "=l"(lo), "=l"(hi) : "r"(addr));
}
__device__ __forceinline__ float hsum2(unsigned long long v) {
    float2 f;
    __builtin_memcpy(&f, &v, 8);
    return f.x + f.y;
}

// ---------------------------------------------------------------------------
// Stage 1: partial[s][b][:] = sum over tokens [s*TOK,(s+1)*TOK) of x[b,t,:]
// HBM-bound: 256 MB read. grid (TS, NB) = 512 blocks, 256 thr, all co-resident.
// ---------------------------------------------------------------------------
__global__ void __launch_bounds__(256) k_reduce(const float* __restrict__ x) {
    const int s = blockIdx.x, b = blockIdx.y, j = threadIdx.x;
    const float4* xp = reinterpret_cast<const float4*>(x)
                     + ((size_t)b * NT + (size_t)s * TOK) * (ND / 4) + j;
    float4 a0 = make_float4(0.f, 0.f, 0.f, 0.f);
    float4 a1 = make_float4(0.f, 0.f, 0.f, 0.f);
    #pragma unroll 4
    for (int t = 0; t < TOK; t += 2) {
        float4 v0 = xp[(size_t)t * (ND / 4)];
        float4 v1 = xp[(size_t)(t + 1) * (ND / 4)];
        a0.x += v0.x; a0.y += v0.y; a0.z += v0.z; a0.w += v0.w;
        a1.x += v1.x; a1.y += v1.y; a1.z += v1.z; a1.w += v1.w;
    }
    float4 r = make_float4(a0.x + a1.x, a0.y + a1.y, a0.z + a1.z, a0.w + a1.w);
    reinterpret_cast<float4*>(g_partial)[(s * NB + b) * (ND / 4) + j] = r;
}

// ---------------------------------------------------------------------------
// GEMM with fused A-partial fold:  dst[b,o] (partial over K-slice)
//   MODE 0: A = sum of TS  g_partial slices, W = W_heads, dst = g_xc[ks]
//   MODE 1: A = sum of KS2 g_xc     slices, W = W_proj,  dst = g_op[ks]
// Block tile 64o x 32b x 128K. grid (16, 8) = 128 blocks, 256 thr.
// Thread (ox=tid&31, bp=tid>>5) owns o in {otile+ox, otile+32+ox},
// b in {4bp..4bp+3}. Accumulators are f32x2 packed ALONG K (even/odd d):
// both FFMA2 operands come straight from smem as 64-bit pairs — no dup MOVs.
// ---------------------------------------------------------------------------
template <int MODE>
__global__ void __launch_bounds__(256) k_gemm(const float* __restrict__ W) {
    __shared__ float4 As[NB * 32];    // [b][d4] 16 KB
    __shared__ float4 Ws[32 * OT];    // [d4][o swizzled] 32 KB
    const int tid    = threadIdx.x;
    const int otile  = blockIdx.x * OT;
    const int kbase4 = blockIdx.y * 32;   // float4 offset of K-slice

    // ---- A tile: fold NS partial sources for this K-slice (coalesced) ----
    {
        const int NS = (MODE == 0) ? TS : KS2;
        const float4* src = reinterpret_cast<const float4*>(
            (MODE == 0) ? g_partial : &g_xc[0][0]);
        #pragma unroll
        for (int k = 0; k < 4; ++k) {
            const int idx = tid + k * 256;          // 1024 slots
            const int b = idx >> 5, d4 = idx & 31;
            float4 v = make_float4(0.f, 0.f, 0.f, 0.f);
            #pragma unroll
            for (int s = 0; s < ((MODE == 0) ? TS : KS2); ++s) {
                float4 u = src[(s * NB + b) * (ND / 4) + kbase4 + d4];
                v.x += u.x; v.y += u.y; v.z += u.z; v.w += u.w;
            }
            (void)NS;
            As[b * 32 + d4] = v;
        }
    }
    // ---- W tile [64 o][32 d4] -> swizzled [d4][(o+d4)&63] ----
    {
        const int o = tid >> 5, d4 = tid & 31;
        #pragma unroll
        for (int r = 0; r < 8; ++r) {
            const int oo = o + r * 8;
            Ws[d4 * OT + ((oo + d4) & 63)] =
                reinterpret_cast<const float4*>(W)[(size_t)(otile + oo) * (ND / 4) + kbase4 + d4];
        }
    }
    __syncthreads();

    const int ox = tid & 31;
    const int bp = tid >> 5;
    const unsigned asBase = (unsigned)__cvta_generic_to_shared(As);
    const unsigned wsBase = (unsigned)__cvta_generic_to_shared(Ws);

    unsigned long long acc[4][2];
    #pragma unroll
    for (int i = 0; i < 4; ++i) { acc[i][0] = 0ull; acc[i][1] = 0ull; }

    #pragma unroll 8
    for (int d4 = 0; d4 < 32; ++d4) {
        unsigned long long w0lo, w0hi, w1lo, w1hi;
        lds_v2u64(w0lo, w0hi, wsBase + (unsigned)((d4 * OT + ((ox + d4) & 63)) << 4));
        lds_v2u64(w1lo, w1hi, wsBase + (unsigned)((d4 * OT + ((ox + 32 + d4) & 63)) << 4));
        #pragma unroll
        for (int i = 0; i < 4; ++i) {
            unsigned long long alo, ahi;   // {A[b,d0],A[b,d1]}, {A[b,d2],A[b,d3]}
            lds_v2u64(alo, ahi, asBase + (unsigned)((((4 * bp + i) * 32 + d4)) << 4));
            ffma2(acc[i][0], alo, w0lo);
            ffma2(acc[i][0], ahi, w0hi);
            ffma2(acc[i][1], alo, w1lo);
            ffma2(acc[i][1], ahi, w1hi);
        }
    }

    float* dst = (MODE == 0) ? g_xc[blockIdx.y] : g_op[blockIdx.y];
    #pragma unroll
    for (int i = 0; i < 4; ++i) {
        const int b = 4 * bp + i;
        dst[b * ND + otile + ox]      = hsum2(acc[i][0]);
        dst[b * ND + otile + 32 + ox] = hsum2(acc[i][1]);
    }
}

// ---------------------------------------------------------------------------
// Epilogue: out[b,c] = sum_p g_op[p][b,c] + bias[c]. 64 blocks x 128 thr.
// ---------------------------------------------------------------------------
__global__ void __launch_bounds__(128) k_epi(const float* __restrict__ bias,
                                             float* __restrict__ out) {
    const int i = blockIdx.x * 128 + threadIdx.x;   // float4 index, 8192 total
    const int c4 = i & (ND / 4 - 1);
    float4 acc = reinterpret_cast<const float4*>(bias)[c4];
    #pragma unroll
    for (int p = 0; p < KS2; ++p) {
        float4 v = reinterpret_cast<const float4*>(g_op[p])[i];
        acc.x += v.x; acc.y += v.y; acc.z += v.z; acc.w += v.w;
    }
    reinterpret_cast<float4*>(out)[i] = acc;
}

// ---------------------------------------------------------------------------
extern "C" void kernel_launch(void* const* d_in, const int* in_sizes, int n_in,
                              void* d_out, int out_size) {
    const float* x  = (const float*)d_in[0];   // [32, 2048, 1024]
    const float* Wh = (const float*)d_in[1];   // [16, 64, 1024] -> flat [1024,1024]
    const float* Wp = (const float*)d_in[2];   // [1024, 1024]
    const float* bp = (const float*)d_in[3];   // [1024]
    float* out = (float*)d_out;                // [32, 1024]

    k_reduce<<<dim3(TS, NB), 256>>>(x);
    k_gemm<0><<<dim3(ND / OT, KS2), 256>>>(Wh);
    k_gemm<1><<<dim3(ND / OT, KS2), 256>>>(Wp);
    k_epi<<<NB * ND / 4 / 128, 128>>>(bp, out);
}